// round 7
// baseline (speedup 1.0000x reference)
#include <cuda_runtime.h>
#include <cstdint>

constexpr int NL  = 6;
constexpr int NH  = 16;
constexpr int DM  = 1024;
constexpr int DH  = 64;
constexpr int DFF = 4096;
constexpr int NV  = 32000;
constexpr int NB  = 2;
constexpr int NS  = 1024;
constexpr int NT  = NB * NS;

__device__ float g_x  [NT * DM];                 // fp32 (residual path)
__device__ float g_xr [NT * DM];                 // tf32-rounded copy
__device__ float g_res[NT * DM];
__device__ float g_qkv[3 * NT * DM];             // rounded
__device__ float g_o  [NT * DM];                 // rounded
__device__ float g_ffn[NT * DFF];                // rounded
__device__ float g_vt [NB * NH * DH * NS];       // rounded V^T per head

__device__ __forceinline__ float f2tff(float f) {
    unsigned u;
    asm("cvt.rna.tf32.f32 %0, %1;" : "=r"(u) : "f"(f));
    return __uint_as_float(u);
}
__device__ __forceinline__ unsigned f2tfu(float f) {
    unsigned u;
    asm("cvt.rna.tf32.f32 %0, %1;" : "=r"(u) : "f"(f));
    return u;
}
__device__ __forceinline__ void mma8(float* c, const uint4& a, unsigned b0, unsigned b1) {
    asm volatile(
        "mma.sync.aligned.m16n8k8.row.col.f32.tf32.tf32.f32 "
        "{%0,%1,%2,%3}, {%4,%5,%6,%7}, {%8,%9}, {%0,%1,%2,%3};"
        : "+f"(c[0]), "+f"(c[1]), "+f"(c[2]), "+f"(c[3])
        : "r"(a.x), "r"(a.y), "r"(a.z), "r"(a.w), "r"(b0), "r"(b1));
}
__device__ __forceinline__ uint4 ldm4(unsigned addr) {
    uint4 r;
    asm volatile("ldmatrix.sync.aligned.m8n8.x4.shared.b16 {%0,%1,%2,%3}, [%4];"
                 : "=r"(r.x), "=r"(r.y), "=r"(r.z), "=r"(r.w) : "r"(addr));
    return r;
}
__device__ __forceinline__ void cp16(unsigned sm, const void* g) {
    asm volatile("cp.async.ca.shared.global [%0], [%1], 16;" :: "r"(sm), "l"(g));
}
#define CP_COMMIT asm volatile("cp.async.commit_group;" ::: "memory")
#define CP_WAIT2  asm volatile("cp.async.wait_group 2;" ::: "memory")
#define CP_WAIT0  asm volatile("cp.async.wait_group 0;" ::: "memory")

// ---------------------------------------------------------------------------
// Transpose + tf32 round (used ONLY for per-head V^T now)
// in (per z: [K][N], ld ldin) -> out[(z*N+n)*K + k]
// ---------------------------------------------------------------------------
__global__ void __launch_bounds__(256)
tr32(const float* __restrict__ in, float* __restrict__ out,
     int K, int N, int ldin, int zdiv, long sZb, long sZh)
{
    __shared__ float t[32][33];
    const int z = blockIdx.z, zb = z / zdiv, zh = z % zdiv;
    in += zb * sZb + zh * sZh;
    const int k0 = blockIdx.x * 32, n0 = blockIdx.y * 32;
    const int tx = threadIdx.x & 31, ty = threadIdx.x >> 5;
    #pragma unroll
    for (int r = 0; r < 32; r += 8)
        t[ty + r][tx] = in[(long)(k0 + ty + r) * ldin + n0 + tx];
    __syncthreads();
    #pragma unroll
    for (int r = 0; r < 32; r += 8)
        out[((long)z * N + n0 + ty + r) * K + k0 + tx] = f2tff(t[tx][ty + r]);
}

// ---------------------------------------------------------------------------
// tf32 TC GEMM, 4-stage cp.async pipeline.
// A: [m][k] fp32 pre-rounded (ldmatrix fragments).
// B: [k][n] fp32 NATIVE weight layout (scalar LDS + cvt.rna fragments).
//    Column n lives at B + (n>>nshift)*sHead + k*ldb + (n & ((1<<nshift)-1)).
// BM=128, BN=128, BK=16, 256 threads (8 warps: 4M x 2N), warp tile 32x64.
// flags: 1=bias, 2=residual, 4=relu, 16=round output
// ---------------------------------------------------------------------------
constexpr int AST = 20;                 // A smem row stride (words)
constexpr int BST = 136;                // B smem row stride (words) - conflict-free
constexpr int ABUF = 128 * AST;         // 2560 words
constexpr int BBUF = 16 * BST;          // 2176 words
constexpr int GSMEM = 4 * (ABUF + BBUF) * 4;   // 75776 bytes

__global__ void __launch_bounds__(256, 2)
gemm_tc(const float* __restrict__ A, const float* __restrict__ B,
        const float* __restrict__ bias, const float* __restrict__ Res,
        float* __restrict__ C, int K, int lda, int ldb, int ldc,
        int nshift, long sHead, int flags)
{
    extern __shared__ unsigned smem[];
    unsigned* Asm = smem;
    float*    Bsm = (float*)(smem + 4 * ABUF);

    const int m0 = blockIdx.x * 128;
    const int n0 = blockIdx.y * 128;
    const int tid = threadIdx.x;

    // A fill (16B cp.async chunks): row=tid/2, 2 chunks of 4 floats
    const int ar = tid >> 1, aw = (tid & 1) * 8;
    const float* Ag = A + (long)(m0 + ar) * lda + aw;
    const unsigned aDst = (unsigned)__cvta_generic_to_shared(&Asm[ar * AST + aw]);

    // B fill: k-row = tid/16 (0..15), col = (tid&15)*8
    const int bk = tid >> 4, bcol = (tid & 15) * 8;
    const int gn = n0 + bcol;
    const float* Bg = B + (long)(gn >> nshift) * sHead + (long)bk * ldb
                        + (gn & ((1 << nshift) - 1));
    const unsigned bDst = (unsigned)__cvta_generic_to_shared(&Bsm[bk * BST + bcol]);

    const int nit = K / 16;
    auto fill = [&](int s) {
        const int st = s & 3;
        const unsigned ao = aDst + st * (ABUF * 4);
        const float* ag = Ag + s * 16;
        cp16(ao, ag); cp16(ao + 16, ag + 4);
        const unsigned bo = bDst + st * (BBUF * 4);
        const float* bg = Bg + (long)s * 16 * ldb;
        cp16(bo, bg); cp16(bo + 16, bg + 4);
    };

    const int lane = tid & 31, wid = tid >> 5;
    const int wm = wid & 3, wn = wid >> 2;
    const int grp = lane >> 2, qd = lane & 3;

    const unsigned aAddr = (unsigned)__cvta_generic_to_shared(
        &Asm[(wm * 32 + (lane & 15)) * AST + ((lane & 16) >> 2)]);
    const int bBase = wn * 64 + grp;     // column within tile for this lane

    float acc[2][8][4];
    #pragma unroll
    for (int i = 0; i < 2; i++)
        #pragma unroll
        for (int j = 0; j < 8; j++)
            #pragma unroll
            for (int l = 0; l < 4; l++) acc[i][j][l] = 0.f;

    #pragma unroll
    for (int s = 0; s < 3; s++) { if (s < nit) fill(s); CP_COMMIT; }

    for (int it = 0; it < nit; it++) {
        CP_WAIT2;
        __syncthreads();
        if (it + 3 < nit) fill(it + 3);
        CP_COMMIT;

        const unsigned aC = aAddr + (it & 3) * (ABUF * 4);
        const float* bs = Bsm + (it & 3) * BBUF;
        #pragma unroll
        for (int ks = 0; ks < 2; ks++) {
            const uint4 a0 = ldm4(aC + (ks * 8) * 4);
            const uint4 a1 = ldm4(aC + (16 * AST + ks * 8) * 4);
            const float* br0 = bs + (ks * 8 + qd) * BST + bBase;
            const float* br1 = br0 + 4 * BST;
            #pragma unroll
            for (int nt = 0; nt < 8; nt++) {
                const unsigned b0 = f2tfu(br0[nt * 8]);
                const unsigned b1 = f2tfu(br1[nt * 8]);
                mma8(acc[0][nt], a0, b0, b1);
                mma8(acc[1][nt], a1, b0, b1);
            }
        }
    }

    const bool dob = flags & 1, dores = flags & 2, dorelu = flags & 4,
               dornd = flags & 16;
    #pragma unroll
    for (int mt = 0; mt < 2; mt++) {
        #pragma unroll
        for (int nt = 0; nt < 8; nt++) {
            const int r = m0 + wm * 32 + mt * 16 + grp;
            const int c = n0 + wn * 64 + nt * 8 + qd * 2;
            #pragma unroll
            for (int hf = 0; hf < 2; hf++) {
                const int rr = r + hf * 8;
                float v0 = acc[mt][nt][hf * 2 + 0];
                float v1 = acc[mt][nt][hf * 2 + 1];
                if (dob) { v0 += bias[c]; v1 += bias[c + 1]; }
                if (dores) {
                    const float* rp = Res + (long)rr * ldc + c;
                    v0 += rp[0]; v1 += rp[1];
                }
                if (dorelu) { v0 = fmaxf(v0, 0.f); v1 = fmaxf(v1, 0.f); }
                if (dornd) { v0 = f2tff(v0); v1 = f2tff(v1); }
                *(float2*)(C + (long)rr * ldc + c) = make_float2(v0, v1);
            }
        }
    }
}

// ---------------------------------------------------------------------------
// Flash attention: 128 q-rows per CTA, 64-wide j tiles, online softmax.
// ---------------------------------------------------------------------------
constexpr int FST = 68;
constexpr int FA_SMEM = (128 * FST + 64 * FST + 64 * FST + 128 * FST) * 4;

__global__ void __launch_bounds__(256, 2)
flash_attn(const float* __restrict__ q, const float* __restrict__ k,
           const float* __restrict__ vt, float* __restrict__ o)
{
    extern __shared__ float fsm[];
    float* Qs  = fsm;
    float* Ks  = Qs  + 128 * FST;
    float* Vts = Ks  + 64 * FST;
    float* Ps  = Vts + 64 * FST;

    const int z = blockIdx.y;
    const int b = z >> 4, h = z & 15;
    const int i0 = blockIdx.x * 128;
    const int tid = threadIdx.x, lane = tid & 31, w = tid >> 5;
    const int grp = lane >> 2, qd = lane & 3;

    {   // Q fill
        const int r = tid >> 1, cb = (tid & 1) * 32;
        const float* src = q + (long)(b * NS + i0 + r) * DM + h * DH + cb;
        unsigned dst = (unsigned)__cvta_generic_to_shared(Qs + r * FST + cb);
        #pragma unroll
        for (int i = 0; i < 8; i++) cp16(dst + i * 16, src + i * 4);
        CP_COMMIT;
    }

    const int r0 = w * 16;
    const int gr = i0 + r0 + grp;
    const unsigned qAddr = (unsigned)__cvta_generic_to_shared(
        Qs + (r0 + (lane & 15)) * FST + ((lane & 16) >> 2));
    const unsigned kAddr = (unsigned)__cvta_generic_to_shared(
        Ks + (lane & 15) * FST + ((lane & 16) >> 2));
    const unsigned vAddr = (unsigned)__cvta_generic_to_shared(
        Vts + (lane & 15) * FST + ((lane & 16) >> 2));
    const unsigned pAddr = (unsigned)__cvta_generic_to_shared(
        Ps + (r0 + (lane & 15)) * FST + ((lane & 16) >> 2));

    float m0 = -1e30f, m1 = -1e30f, l0 = 0.f, l1 = 0.f;
    float oacc[8][4];
    #pragma unroll
    for (int i = 0; i < 8; i++)
        #pragma unroll
        for (int j = 0; j < 4; j++) oacc[i][j] = 0.f;

    const int ntiles = i0 / 64 + 2;

    for (int jt = 0; jt < ntiles; jt++) {
        const int j0 = jt * 64;
        __syncthreads();
        {
            const int jj = tid >> 2, cb = (tid & 3) * 4;
            const float* ks = k + (long)(b * NS + j0 + jj) * DM + h * DH + cb;
            unsigned kd = (unsigned)__cvta_generic_to_shared(Ks + jj * FST + cb);
            #pragma unroll
            for (int i = 0; i < 4; i++) cp16(kd + i * 64, ks + i * 16);
            const float* vs = vt + ((long)z * DH + jj) * NS + j0 + cb;
            unsigned vd = (unsigned)__cvta_generic_to_shared(Vts + jj * FST + cb);
            #pragma unroll
            for (int i = 0; i < 4; i++) cp16(vd + i * 64, vs + i * 16);
            CP_COMMIT;
        }
        CP_WAIT0;
        __syncthreads();

        if (j0 <= i0 + r0 + 15) {
            float sacc[8][4];
            #pragma unroll
            for (int i = 0; i < 8; i++)
                #pragma unroll
                for (int j = 0; j < 4; j++) sacc[i][j] = 0.f;

            #pragma unroll
            for (int ks = 0; ks < 8; ks++) {
                const uint4 af = ldm4(qAddr + (ks * 8) * 4);
                #pragma unroll
                for (int p = 0; p < 4; p++) {
                    const uint4 bv = ldm4(kAddr + (p * 16 * FST + ks * 8) * 4);
                    mma8(sacc[2 * p],     af, bv.x, bv.z);
                    mma8(sacc[2 * p + 1], af, bv.y, bv.w);
                }
            }

            float mx0 = -1e30f, mx1 = -1e30f;
            #pragma unroll
            for (int nt = 0; nt < 8; nt++) {
                const int jc = j0 + nt * 8 + qd * 2;
                float v0 = sacc[nt][0] * 0.125f, v1 = sacc[nt][1] * 0.125f;
                float v2 = sacc[nt][2] * 0.125f, v3 = sacc[nt][3] * 0.125f;
                if (jc     > gr)     v0 = -1e30f;
                if (jc + 1 > gr)     v1 = -1e30f;
                if (jc     > gr + 8) v2 = -1e30f;
                if (jc + 1 > gr + 8) v3 = -1e30f;
                sacc[nt][0] = v0; sacc[nt][1] = v1; sacc[nt][2] = v2; sacc[nt][3] = v3;
                mx0 = fmaxf(mx0, fmaxf(v0, v1));
                mx1 = fmaxf(mx1, fmaxf(v2, v3));
            }
            mx0 = fmaxf(mx0, __shfl_xor_sync(0xffffffffu, mx0, 1));
            mx0 = fmaxf(mx0, __shfl_xor_sync(0xffffffffu, mx0, 2));
            mx1 = fmaxf(mx1, __shfl_xor_sync(0xffffffffu, mx1, 1));
            mx1 = fmaxf(mx1, __shfl_xor_sync(0xffffffffu, mx1, 2));
            const float mn0 = fmaxf(m0, mx0), mn1 = fmaxf(m1, mx1);
            const float es0 = expf(m0 - mn0), es1 = expf(m1 - mn1);
            m0 = mn0; m1 = mn1;

            float rs0 = 0.f, rs1 = 0.f;
            const int lr = r0 + grp;
            #pragma unroll
            for (int nt = 0; nt < 8; nt++) {
                const float p0 = expf(sacc[nt][0] - mn0);
                const float p1 = expf(sacc[nt][1] - mn0);
                const float p2 = expf(sacc[nt][2] - mn1);
                const float p3 = expf(sacc[nt][3] - mn1);
                rs0 += p0 + p1; rs1 += p2 + p3;
                *(float2*)(Ps + lr * FST + nt * 8 + qd * 2) =
                    make_float2(f2tff(p0), f2tff(p1));
                *(float2*)(Ps + (lr + 8) * FST + nt * 8 + qd * 2) =
                    make_float2(f2tff(p2), f2tff(p3));
            }
            rs0 += __shfl_xor_sync(0xffffffffu, rs0, 1);
            rs0 += __shfl_xor_sync(0xffffffffu, rs0, 2);
            rs1 += __shfl_xor_sync(0xffffffffu, rs1, 1);
            rs1 += __shfl_xor_sync(0xffffffffu, rs1, 2);
            l0 = l0 * es0 + rs0;
            l1 = l1 * es1 + rs1;

            #pragma unroll
            for (int nt = 0; nt < 8; nt++) {
                oacc[nt][0] *= es0; oacc[nt][1] *= es0;
                oacc[nt][2] *= es1; oacc[nt][3] *= es1;
            }
            __syncwarp();

            #pragma unroll
            for (int ks = 0; ks < 8; ks++) {
                const uint4 pf = ldm4(pAddr + (ks * 8) * 4);
                #pragma unroll
                for (int p = 0; p < 4; p++) {
                    const uint4 bv = ldm4(vAddr + (p * 16 * FST + ks * 8) * 4);
                    mma8(oacc[2 * p],     pf, bv.x, bv.z);
                    mma8(oacc[2 * p + 1], pf, bv.y, bv.w);
                }
            }
        }
    }

    const float inv0 = 1.f / l0, inv1 = 1.f / l1;
    #pragma unroll
    for (int nt = 0; nt < 8; nt++) {
        const int c = h * DH + nt * 8 + qd * 2;
        *(float2*)(o + (long)(b * NS + gr) * DM + c) =
            make_float2(f2tff(oacc[nt][0] * inv0), f2tff(oacc[nt][1] * inv0));
        *(float2*)(o + (long)(b * NS + gr + 8) * DM + c) =
            make_float2(f2tff(oacc[nt][2] * inv1), f2tff(oacc[nt][3] * inv1));
    }
}

// ---------------------------------------------------------------------------
__global__ void __launch_bounds__(256)
ln_kernel(const float* __restrict__ in, const float* __restrict__ g,
          const float* __restrict__ b, float* __restrict__ out,
          float* __restrict__ outr)
{
    const float* p = in + (long)blockIdx.x * DM;
    float* po  = out  + (long)blockIdx.x * DM;
    float* por = outr + (long)blockIdx.x * DM;
    const int tid = threadIdx.x;
    __shared__ float red[256];
    float vals[4];
    float s = 0.f;
    #pragma unroll
    for (int i = 0; i < 4; i++) { vals[i] = p[tid + i * 256]; s += vals[i]; }
    red[tid] = s; __syncthreads();
    for (int st = 128; st > 0; st >>= 1) {
        if (tid < st) red[tid] += red[tid + st];
        __syncthreads();
    }
    const float mean = red[0] * (1.f / DM); __syncthreads();
    float sq = 0.f;
    #pragma unroll
    for (int i = 0; i < 4; i++) { float d = vals[i] - mean; sq += d * d; }
    red[tid] = sq; __syncthreads();
    for (int st = 128; st > 0; st >>= 1) {
        if (tid < st) red[tid] += red[tid + st];
        __syncthreads();
    }
    const float sd = sqrtf(red[0] / (DM - 1));
    const float inv = 1.f / (sd + 1e-6f);
    #pragma unroll
    for (int i = 0; i < 4; i++) {
        const int d = tid + i * 256;
        const float r = g[d] * (vals[i] - mean) * inv + b[d];
        po[d] = r;
        por[d] = f2tff(r);
    }
}

__global__ void __launch_bounds__(256)
embed_kernel(const int* __restrict__ tokens, const float* __restrict__ emb,
             float* __restrict__ x, float* __restrict__ xr)
{
    const int t = blockIdx.x;
    const int s = t & (NS - 1);
    const float* e = emb + (long)tokens[t] * DM;
    float* xo  = x  + (long)t * DM;
    float* xro = xr + (long)t * DM;
    const float nlog = -9.210340371976184f / (float)DM;
    for (int d = threadIdx.x; d < DM; d += 256) {
        const float freq = expf((float)(d & ~1) * nlog);
        const float ang = (float)s * freq;
        const float r = e[d] * 32.0f + ((d & 1) ? cosf(ang) : sinf(ang));
        xo[d] = r;
        xro[d] = f2tff(r);
    }
}

// ---------------------------------------------------------------------------
extern "C" void kernel_launch(void* const* d_in, const int* in_sizes, int n_in,
                              void* d_out, int out_size)
{
    const int*   tokens = (const int*)  d_in[0];
    const float* emb    = (const float*)d_in[1];
    const float* Wq     = (const float*)d_in[2];
    const float* Wk     = (const float*)d_in[3];
    const float* Wv     = (const float*)d_in[4];
    const float* Wo     = (const float*)d_in[5];
    const float* bo     = (const float*)d_in[6];
    const float* ln1g   = (const float*)d_in[7];
    const float* ln1b   = (const float*)d_in[8];
    const float* W1     = (const float*)d_in[9];
    const float* b1     = (const float*)d_in[10];
    const float* W2     = (const float*)d_in[11];
    const float* b2     = (const float*)d_in[12];
    const float* ln2g   = (const float*)d_in[13];
    const float* ln2b   = (const float*)d_in[14];
    const float* Wout   = (const float*)d_in[15];
    const float* bout   = (const float*)d_in[16];
    float* out = (float*)d_out;

    float *x, *xr, *res, *qkv, *o, *ffn, *vt;
    cudaGetSymbolAddress((void**)&x,   g_x);
    cudaGetSymbolAddress((void**)&xr,  g_xr);
    cudaGetSymbolAddress((void**)&res, g_res);
    cudaGetSymbolAddress((void**)&qkv, g_qkv);
    cudaGetSymbolAddress((void**)&o,   g_o);
    cudaGetSymbolAddress((void**)&ffn, g_ffn);
    cudaGetSymbolAddress((void**)&vt,  g_vt);

    cudaFuncSetAttribute(gemm_tc,    cudaFuncAttributeMaxDynamicSharedMemorySize, GSMEM);
    cudaFuncSetAttribute(flash_attn, cudaFuncAttributeMaxDynamicSharedMemorySize, FA_SMEM);

    float* q = qkv;
    float* k = qkv + NT * DM;
    float* v = qkv + 2 * NT * DM;
    const long HW = (long)NH * DM * DH;

    embed_kernel<<<NT, 256>>>(tokens, emb, x, xr);

    for (int l = 0; l < NL; l++) {
        // QKV: weights consumed natively [h][k][dh]; B col n -> head n>>6, dh n&63
        gemm_tc<<<dim3(NT / 128, DM / 128), 256, GSMEM>>>(
            xr, Wq + l * HW, nullptr, nullptr, q, DM, DM, DH, DM,
            6, (long)DM * DH, 16);
        gemm_tc<<<dim3(NT / 128, DM / 128), 256, GSMEM>>>(
            xr, Wk + l * HW, nullptr, nullptr, k, DM, DM, DH, DM,
            6, (long)DM * DH, 16);
        gemm_tc<<<dim3(NT / 128, DM / 128), 256, GSMEM>>>(
            xr, Wv + l * HW, nullptr, nullptr, v, DM, DM, DH, DM,
            6, (long)DM * DH, 16);

        // V^T per head (rounded)
        tr32<<<dim3(NS / 32, DH / 32, NB * NH), 256>>>(
            v, vt, NS, DH, DM, NH, (long)NS * DM, DH);

        // flash attention -> o (rounded)
        flash_attn<<<dim3(NS / 128, NB * NH), 256, FA_SMEM>>>(q, k, vt, o);

        // O projection + bias + residual (fp32 out)
        gemm_tc<<<dim3(NT / 128, DM / 128), 256, GSMEM>>>(
            o, Wo + (long)l * DM * DM, bo + l * DM, x, res, DM, DM, DM, DM,
            30, 0, 1 | 2);
        ln_kernel<<<NT, 256>>>(res, ln1g + l * DM, ln1b + l * DM, x, xr);

        // FFN
        gemm_tc<<<dim3(NT / 128, DFF / 128), 256, GSMEM>>>(
            xr, W1 + (long)l * DM * DFF, b1 + l * DFF, nullptr, ffn,
            DM, DM, DFF, DFF, 30, 0, 1 | 4 | 16);
        gemm_tc<<<dim3(NT / 128, DM / 128), 256, GSMEM>>>(
            ffn, W2 + (long)l * DFF * DM, b2 + l * DM, x, res,
            DFF, DFF, DM, DM, 30, 0, 1 | 2);
        ln_kernel<<<NT, 256>>>(res, ln2g + l * DM, ln2b + l * DM, x, xr);
    }

    gemm_tc<<<dim3(NT / 128, NV / 128), 256, GSMEM>>>(
        xr, Wout, bout, nullptr, out, DM, DM, NV, NV, 30, 0, 1);
}

// round 8
// speedup vs baseline: 1.0861x; 1.0861x over previous
#include <cuda_runtime.h>
#include <cstdint>

constexpr int NL  = 6;
constexpr int NH  = 16;
constexpr int DM  = 1024;
constexpr int DH  = 64;
constexpr int DFF = 4096;
constexpr int NV  = 32000;
constexpr int NB  = 2;
constexpr int NS  = 1024;
constexpr int NT  = NB * NS;

__device__ float g_x  [NT * DM];                 // fp32 (residual path)
__device__ float g_xr [NT * DM];                 // tf32-rounded copy
__device__ float g_res[NT * DM];
__device__ float g_qkv[3 * NT * DM];             // rounded
__device__ float g_o  [NT * DM];                 // rounded
__device__ float g_ffn[NT * DFF];                // rounded
__device__ float g_vt [NB * NH * DH * NS];       // rounded V^T per head
__device__ float g_bt [(long)NV * DM];           // rounded transposed weights

__device__ __forceinline__ float f2tff(float f) {
    unsigned u;
    asm("cvt.rna.tf32.f32 %0, %1;" : "=r"(u) : "f"(f));
    return __uint_as_float(u);
}
__device__ __forceinline__ void mma8(float* c, const uint4& a, unsigned b0, unsigned b1) {
    asm volatile(
        "mma.sync.aligned.m16n8k8.row.col.f32.tf32.tf32.f32 "
        "{%0,%1,%2,%3}, {%4,%5,%6,%7}, {%8,%9}, {%0,%1,%2,%3};"
        : "+f"(c[0]), "+f"(c[1]), "+f"(c[2]), "+f"(c[3])
        : "r"(a.x), "r"(a.y), "r"(a.z), "r"(a.w), "r"(b0), "r"(b1));
}
__device__ __forceinline__ uint4 ldm4(unsigned addr) {
    uint4 r;
    asm volatile("ldmatrix.sync.aligned.m8n8.x4.shared.b16 {%0,%1,%2,%3}, [%4];"
                 : "=r"(r.x), "=r"(r.y), "=r"(r.z), "=r"(r.w) : "r"(addr));
    return r;
}
__device__ __forceinline__ void cp16(unsigned sm, const void* g) {
    asm volatile("cp.async.ca.shared.global [%0], [%1], 16;" :: "r"(sm), "l"(g));
}
#define CP_COMMIT asm volatile("cp.async.commit_group;" ::: "memory")
#define CP_WAIT1  asm volatile("cp.async.wait_group 1;" ::: "memory")
#define CP_WAIT0  asm volatile("cp.async.wait_group 0;" ::: "memory")

// ---------------------------------------------------------------------------
// Vectorized transpose + tf32 round.
// in (per z: [K][N], row stride ldin) -> out[(z*N + n)*K + k]
// 32x32 tile per CTA, float4 both sides, padded smem (conflict-free).
// Requires K%32==0, N%32==0, ldin%4==0, base offsets 16B-aligned.
// ---------------------------------------------------------------------------
__global__ void __launch_bounds__(256)
tr32v(const float* __restrict__ in, float* __restrict__ out,
      int K, int N, int ldin, int zdiv, long sZb, long sZh)
{
    __shared__ float t[32][33];
    const int z = blockIdx.z, zb = z / zdiv, zh = z % zdiv;
    in += zb * sZb + zh * sZh;
    const int k0 = blockIdx.x * 32, n0 = blockIdx.y * 32;
    const int r = threadIdx.x >> 3, c = (threadIdx.x & 7) * 4;

    const float4 v = *(const float4*)&in[(long)(k0 + r) * ldin + n0 + c];
    t[r][c] = v.x; t[r][c + 1] = v.y; t[r][c + 2] = v.z; t[r][c + 3] = v.w;
    __syncthreads();

    float4 o4;
    o4.x = f2tff(t[c + 0][r]);
    o4.y = f2tff(t[c + 1][r]);
    o4.z = f2tff(t[c + 2][r]);
    o4.w = f2tff(t[c + 3][r]);
    *(float4*)&out[((long)z * N + n0 + r) * K + k0 + c] = o4;
}

// ---------------------------------------------------------------------------
// tf32 TC GEMM: 3-stage cp.async pipeline, ldmatrix both operands.
// A [m][k] pre-rounded fp32, Bt [n][k] pre-rounded fp32.
// BM=128, BN=128, BK=16, 256 threads (8 warps: 4M x 2N), warp tile 32x64.
// flags: 1=bias, 2=residual, 4=relu, 16=round output
// ---------------------------------------------------------------------------
constexpr int ST   = 20;
constexpr int ABUF = 128 * ST;
constexpr int BBUF = 128 * ST;
constexpr int GSMEM = 3 * (ABUF + BBUF) * 4;   // 61440 bytes -> 2 CTAs/SM

__global__ void __launch_bounds__(256, 2)
gemm_tc(const float* __restrict__ A, const float* __restrict__ Bt,
        const float* __restrict__ bias, const float* __restrict__ Res,
        float* __restrict__ C, int K, int lda, int ldb, int ldc, int zdiv,
        long sAb, long sAh, long sBb, long sBh, long sCb, long sCh,
        int flags)
{
    extern __shared__ unsigned smem[];
    unsigned* Asm = smem;
    unsigned* Bsm = smem + 3 * ABUF;

    const int zb = blockIdx.z / zdiv, zh = blockIdx.z % zdiv;
    A  += zb * sAb + zh * sAh;
    Bt += zb * sBb + zh * sBh;
    const long coff = (long)zb * sCb + (long)zh * sCh;

    const int m0 = blockIdx.x * 128;
    const int n0 = blockIdx.y * 128;
    const int tid = threadIdx.x;

    const int ar = tid >> 1, aw = (tid & 1) * 8;
    const float* Ag = A + (long)(m0 + ar) * lda + aw;
    const unsigned aDst = (unsigned)__cvta_generic_to_shared(&Asm[ar * ST + aw]);
    const float* Bg = Bt + (long)(n0 + ar) * ldb + aw;
    const unsigned bDst = (unsigned)__cvta_generic_to_shared(&Bsm[ar * ST + aw]);

    const int nit = K / 16;
    auto fill = [&](int s) {
        const int st = s % 3;
        const unsigned ao = aDst + st * (ABUF * 4);
        const float* ag = Ag + s * 16;
        cp16(ao, ag); cp16(ao + 16, ag + 4);
        const unsigned bo = bDst + st * (BBUF * 4);
        const float* bg = Bg + s * 16;
        cp16(bo, bg); cp16(bo + 16, bg + 4);
    };

    const int lane = tid & 31, wid = tid >> 5;
    const int wm = wid & 3, wn = wid >> 2;
    const int grp = lane >> 2, qd = lane & 3;

    const unsigned aAddr = (unsigned)__cvta_generic_to_shared(
        &Asm[(wm * 32 + (lane & 15)) * ST + ((lane & 16) >> 2)]);
    const unsigned bAddr = (unsigned)__cvta_generic_to_shared(
        &Bsm[(wn * 64 + (lane & 15)) * ST + ((lane & 16) >> 2)]);

    float acc[2][8][4];
    #pragma unroll
    for (int i = 0; i < 2; i++)
        #pragma unroll
        for (int j = 0; j < 8; j++)
            #pragma unroll
            for (int l = 0; l < 4; l++) acc[i][j][l] = 0.f;

    fill(0); CP_COMMIT;
    if (nit > 1) fill(1);
    CP_COMMIT;

    for (int it = 0; it < nit; it++) {
        CP_WAIT1;
        __syncthreads();
        if (it + 2 < nit) fill(it + 2);
        CP_COMMIT;

        const int st = it % 3;
        const unsigned aC = aAddr + st * (ABUF * 4);
        const unsigned bC = bAddr + st * (BBUF * 4);
        #pragma unroll
        for (int ks = 0; ks < 2; ks++) {
            const uint4 a0 = ldm4(aC + (ks * 8) * 4);
            const uint4 a1 = ldm4(aC + (16 * ST + ks * 8) * 4);
            #pragma unroll
            for (int p = 0; p < 4; p++) {
                const uint4 bv = ldm4(bC + (p * 16 * ST + ks * 8) * 4);
                mma8(acc[0][2 * p],     a0, bv.x, bv.z);
                mma8(acc[0][2 * p + 1], a0, bv.y, bv.w);
                mma8(acc[1][2 * p],     a1, bv.x, bv.z);
                mma8(acc[1][2 * p + 1], a1, bv.y, bv.w);
            }
        }
    }

    const bool dob = flags & 1, dores = flags & 2, dorelu = flags & 4,
               dornd = flags & 16;
    #pragma unroll
    for (int mt = 0; mt < 2; mt++) {
        #pragma unroll
        for (int nt = 0; nt < 8; nt++) {
            const int r = m0 + wm * 32 + mt * 16 + grp;
            const int c = n0 + wn * 64 + nt * 8 + qd * 2;
            #pragma unroll
            for (int hf = 0; hf < 2; hf++) {
                const int rr = r + hf * 8;
                float v0 = acc[mt][nt][hf * 2 + 0];
                float v1 = acc[mt][nt][hf * 2 + 1];
                if (dob) { v0 += bias[c]; v1 += bias[c + 1]; }
                if (dores) {
                    const float* rp = Res + coff + (long)rr * ldc + c;
                    v0 += rp[0]; v1 += rp[1];
                }
                if (dorelu) { v0 = fmaxf(v0, 0.f); v1 = fmaxf(v1, 0.f); }
                if (dornd) { v0 = f2tff(v0); v1 = f2tff(v1); }
                *(float2*)(C + coff + (long)rr * ldc + c) = make_float2(v0, v1);
            }
        }
    }
}

// ---------------------------------------------------------------------------
// Flash attention: 128 q-rows per CTA, 64-wide j tiles, online softmax.
// ---------------------------------------------------------------------------
constexpr int FST = 68;
constexpr int FA_SMEM = (128 * FST + 64 * FST + 64 * FST + 128 * FST) * 4;

__global__ void __launch_bounds__(256, 2)
flash_attn(const float* __restrict__ q, const float* __restrict__ k,
           const float* __restrict__ vt, float* __restrict__ o)
{
    extern __shared__ float fsm[];
    float* Qs  = fsm;
    float* Ks  = Qs  + 128 * FST;
    float* Vts = Ks  + 64 * FST;
    float* Ps  = Vts + 64 * FST;

    const int z = blockIdx.y;
    const int b = z >> 4, h = z & 15;
    const int i0 = blockIdx.x * 128;
    const int tid = threadIdx.x, lane = tid & 31, w = tid >> 5;
    const int grp = lane >> 2, qd = lane & 3;

    {   // Q fill
        const int r = tid >> 1, cb = (tid & 1) * 32;
        const float* src = q + (long)(b * NS + i0 + r) * DM + h * DH + cb;
        unsigned dst = (unsigned)__cvta_generic_to_shared(Qs + r * FST + cb);
        #pragma unroll
        for (int i = 0; i < 8; i++) cp16(dst + i * 16, src + i * 4);
        CP_COMMIT;
    }

    const int r0 = w * 16;
    const int gr = i0 + r0 + grp;
    const unsigned qAddr = (unsigned)__cvta_generic_to_shared(
        Qs + (r0 + (lane & 15)) * FST + ((lane & 16) >> 2));
    const unsigned kAddr = (unsigned)__cvta_generic_to_shared(
        Ks + (lane & 15) * FST + ((lane & 16) >> 2));
    const unsigned vAddr = (unsigned)__cvta_generic_to_shared(
        Vts + (lane & 15) * FST + ((lane & 16) >> 2));
    const unsigned pAddr = (unsigned)__cvta_generic_to_shared(
        Ps + (r0 + (lane & 15)) * FST + ((lane & 16) >> 2));

    float m0 = -1e30f, m1 = -1e30f, l0 = 0.f, l1 = 0.f;
    float oacc[8][4];
    #pragma unroll
    for (int i = 0; i < 8; i++)
        #pragma unroll
        for (int j = 0; j < 4; j++) oacc[i][j] = 0.f;

    const int ntiles = i0 / 64 + 2;

    for (int jt = 0; jt < ntiles; jt++) {
        const int j0 = jt * 64;
        __syncthreads();
        {
            const int jj = tid >> 2, cb = (tid & 3) * 4;
            const float* ks = k + (long)(b * NS + j0 + jj) * DM + h * DH + cb;
            unsigned kd = (unsigned)__cvta_generic_to_shared(Ks + jj * FST + cb);
            #pragma unroll
            for (int i = 0; i < 4; i++) cp16(kd + i * 64, ks + i * 16);
            const float* vs = vt + ((long)z * DH + jj) * NS + j0 + cb;
            unsigned vd = (unsigned)__cvta_generic_to_shared(Vts + jj * FST + cb);
            #pragma unroll
            for (int i = 0; i < 4; i++) cp16(vd + i * 64, vs + i * 16);
            CP_COMMIT;
        }
        CP_WAIT0;
        __syncthreads();

        if (j0 <= i0 + r0 + 15) {
            float sacc[8][4];
            #pragma unroll
            for (int i = 0; i < 8; i++)
                #pragma unroll
                for (int j = 0; j < 4; j++) sacc[i][j] = 0.f;

            #pragma unroll
            for (int ks = 0; ks < 8; ks++) {
                const uint4 af = ldm4(qAddr + (ks * 8) * 4);
                #pragma unroll
                for (int p = 0; p < 4; p++) {
                    const uint4 bv = ldm4(kAddr + (p * 16 * FST + ks * 8) * 4);
                    mma8(sacc[2 * p],     af, bv.x, bv.z);
                    mma8(sacc[2 * p + 1], af, bv.y, bv.w);
                }
            }

            float mx0 = -1e30f, mx1 = -1e30f;
            #pragma unroll
            for (int nt = 0; nt < 8; nt++) {
                const int jc = j0 + nt * 8 + qd * 2;
                float v0 = sacc[nt][0] * 0.125f, v1 = sacc[nt][1] * 0.125f;
                float v2 = sacc[nt][2] * 0.125f, v3 = sacc[nt][3] * 0.125f;
                if (jc     > gr)     v0 = -1e30f;
                if (jc + 1 > gr)     v1 = -1e30f;
                if (jc     > gr + 8) v2 = -1e30f;
                if (jc + 1 > gr + 8) v3 = -1e30f;
                sacc[nt][0] = v0; sacc[nt][1] = v1; sacc[nt][2] = v2; sacc[nt][3] = v3;
                mx0 = fmaxf(mx0, fmaxf(v0, v1));
                mx1 = fmaxf(mx1, fmaxf(v2, v3));
            }
            mx0 = fmaxf(mx0, __shfl_xor_sync(0xffffffffu, mx0, 1));
            mx0 = fmaxf(mx0, __shfl_xor_sync(0xffffffffu, mx0, 2));
            mx1 = fmaxf(mx1, __shfl_xor_sync(0xffffffffu, mx1, 1));
            mx1 = fmaxf(mx1, __shfl_xor_sync(0xffffffffu, mx1, 2));
            const float mn0 = fmaxf(m0, mx0), mn1 = fmaxf(m1, mx1);
            const float es0 = expf(m0 - mn0), es1 = expf(m1 - mn1);
            m0 = mn0; m1 = mn1;

            float rs0 = 0.f, rs1 = 0.f;
            const int lr = r0 + grp;
            #pragma unroll
            for (int nt = 0; nt < 8; nt++) {
                const float p0 = expf(sacc[nt][0] - mn0);
                const float p1 = expf(sacc[nt][1] - mn0);
                const float p2 = expf(sacc[nt][2] - mn1);
                const float p3 = expf(sacc[nt][3] - mn1);
                rs0 += p0 + p1; rs1 += p2 + p3;
                *(float2*)(Ps + lr * FST + nt * 8 + qd * 2) =
                    make_float2(f2tff(p0), f2tff(p1));
                *(float2*)(Ps + (lr + 8) * FST + nt * 8 + qd * 2) =
                    make_float2(f2tff(p2), f2tff(p3));
            }
            rs0 += __shfl_xor_sync(0xffffffffu, rs0, 1);
            rs0 += __shfl_xor_sync(0xffffffffu, rs0, 2);
            rs1 += __shfl_xor_sync(0xffffffffu, rs1, 1);
            rs1 += __shfl_xor_sync(0xffffffffu, rs1, 2);
            l0 = l0 * es0 + rs0;
            l1 = l1 * es1 + rs1;

            #pragma unroll
            for (int nt = 0; nt < 8; nt++) {
                oacc[nt][0] *= es0; oacc[nt][1] *= es0;
                oacc[nt][2] *= es1; oacc[nt][3] *= es1;
            }
            __syncwarp();

            #pragma unroll
            for (int ks = 0; ks < 8; ks++) {
                const uint4 pf = ldm4(pAddr + (ks * 8) * 4);
                #pragma unroll
                for (int p = 0; p < 4; p++) {
                    const uint4 bv = ldm4(vAddr + (p * 16 * FST + ks * 8) * 4);
                    mma8(oacc[2 * p],     pf, bv.x, bv.z);
                    mma8(oacc[2 * p + 1], pf, bv.y, bv.w);
                }
            }
        }
    }

    const float inv0 = 1.f / l0, inv1 = 1.f / l1;
    #pragma unroll
    for (int nt = 0; nt < 8; nt++) {
        const int c = h * DH + nt * 8 + qd * 2;
        *(float2*)(o + (long)(b * NS + gr) * DM + c) =
            make_float2(f2tff(oacc[nt][0] * inv0), f2tff(oacc[nt][1] * inv0));
        *(float2*)(o + (long)(b * NS + gr + 8) * DM + c) =
            make_float2(f2tff(oacc[nt][2] * inv1), f2tff(oacc[nt][3] * inv1));
    }
}

// ---------------------------------------------------------------------------
__global__ void __launch_bounds__(256)
ln_kernel(const float* __restrict__ in, const float* __restrict__ g,
          const float* __restrict__ b, float* __restrict__ out,
          float* __restrict__ outr)
{
    const float* p = in + (long)blockIdx.x * DM;
    float* po  = out  + (long)blockIdx.x * DM;
    float* por = outr + (long)blockIdx.x * DM;
    const int tid = threadIdx.x;
    __shared__ float red[256];
    float vals[4];
    float s = 0.f;
    #pragma unroll
    for (int i = 0; i < 4; i++) { vals[i] = p[tid + i * 256]; s += vals[i]; }
    red[tid] = s; __syncthreads();
    for (int st = 128; st > 0; st >>= 1) {
        if (tid < st) red[tid] += red[tid + st];
        __syncthreads();
    }
    const float mean = red[0] * (1.f / DM); __syncthreads();
    float sq = 0.f;
    #pragma unroll
    for (int i = 0; i < 4; i++) { float d = vals[i] - mean; sq += d * d; }
    red[tid] = sq; __syncthreads();
    for (int st = 128; st > 0; st >>= 1) {
        if (tid < st) red[tid] += red[tid + st];
        __syncthreads();
    }
    const float sd = sqrtf(red[0] / (DM - 1));
    const float inv = 1.f / (sd + 1e-6f);
    #pragma unroll
    for (int i = 0; i < 4; i++) {
        const int d = tid + i * 256;
        const float r = g[d] * (vals[i] - mean) * inv + b[d];
        po[d] = r;
        por[d] = f2tff(r);
    }
}

__global__ void __launch_bounds__(256)
embed_kernel(const int* __restrict__ tokens, const float* __restrict__ emb,
             float* __restrict__ x, float* __restrict__ xr)
{
    const int t = blockIdx.x;
    const int s = t & (NS - 1);
    const float* e = emb + (long)tokens[t] * DM;
    float* xo  = x  + (long)t * DM;
    float* xro = xr + (long)t * DM;
    const float nlog = -9.210340371976184f / (float)DM;
    for (int d = threadIdx.x; d < DM; d += 256) {
        const float freq = expf((float)(d & ~1) * nlog);
        const float ang = (float)s * freq;
        const float r = e[d] * 32.0f + ((d & 1) ? cosf(ang) : sinf(ang));
        xo[d] = r;
        xro[d] = f2tff(r);
    }
}

// ---------------------------------------------------------------------------
extern "C" void kernel_launch(void* const* d_in, const int* in_sizes, int n_in,
                              void* d_out, int out_size)
{
    const int*   tokens = (const int*)  d_in[0];
    const float* emb    = (const float*)d_in[1];
    const float* Wq     = (const float*)d_in[2];
    const float* Wk     = (const float*)d_in[3];
    const float* Wv     = (const float*)d_in[4];
    const float* Wo     = (const float*)d_in[5];
    const float* bo     = (const float*)d_in[6];
    const float* ln1g   = (const float*)d_in[7];
    const float* ln1b   = (const float*)d_in[8];
    const float* W1     = (const float*)d_in[9];
    const float* b1     = (const float*)d_in[10];
    const float* W2     = (const float*)d_in[11];
    const float* b2     = (const float*)d_in[12];
    const float* ln2g   = (const float*)d_in[13];
    const float* ln2b   = (const float*)d_in[14];
    const float* Wout   = (const float*)d_in[15];
    const float* bout   = (const float*)d_in[16];
    float* out = (float*)d_out;

    float *x, *xr, *res, *qkv, *o, *ffn, *vt, *bt;
    cudaGetSymbolAddress((void**)&x,   g_x);
    cudaGetSymbolAddress((void**)&xr,  g_xr);
    cudaGetSymbolAddress((void**)&res, g_res);
    cudaGetSymbolAddress((void**)&qkv, g_qkv);
    cudaGetSymbolAddress((void**)&o,   g_o);
    cudaGetSymbolAddress((void**)&ffn, g_ffn);
    cudaGetSymbolAddress((void**)&vt,  g_vt);
    cudaGetSymbolAddress((void**)&bt,  g_bt);

    cudaFuncSetAttribute(gemm_tc,    cudaFuncAttributeMaxDynamicSharedMemorySize, GSMEM);
    cudaFuncSetAttribute(flash_attn, cudaFuncAttributeMaxDynamicSharedMemorySize, FA_SMEM);

    float* q = qkv;
    float* k = qkv + NT * DM;
    float* v = qkv + 2 * NT * DM;
    const long HW = (long)NH * DM * DH;

    embed_kernel<<<NT, 256>>>(tokens, emb, x, xr);

    for (int l = 0; l < NL; l++) {
        // QKV weights -> bt[(h*64+n)*DM + k] (rounded), fused z=3 GEMM
        tr32v<<<dim3(DM / 32, DH / 32, NH), 256>>>(Wq + l * HW, bt,          DM, DH, DH, NH, 0, (long)DM * DH);
        tr32v<<<dim3(DM / 32, DH / 32, NH), 256>>>(Wk + l * HW, bt + HW,     DM, DH, DH, NH, 0, (long)DM * DH);
        tr32v<<<dim3(DM / 32, DH / 32, NH), 256>>>(Wv + l * HW, bt + 2 * HW, DM, DH, DH, NH, 0, (long)DM * DH);
        gemm_tc<<<dim3(NT / 128, DM / 128, 3), 256, GSMEM>>>(
            xr, bt, nullptr, nullptr, qkv, DM, DM, DM, DM, 3,
            0, 0, 0, HW, 0, (long)NT * DM, 16);

        // V^T per head (rounded)
        tr32v<<<dim3(NS / 32, DH / 32, NB * NH), 256>>>(
            v, vt, NS, DH, DM, NH, (long)NS * DM, DH);

        // flash attention -> o (rounded)
        flash_attn<<<dim3(NS / 128, NB * NH), 256, FA_SMEM>>>(q, k, vt, o);

        // O projection + bias + residual (fp32 out)
        tr32v<<<dim3(DM / 32, DM / 32, 1), 256>>>(Wo + (long)l * DM * DM, bt, DM, DM, DM, 1, 0, 0);
        gemm_tc<<<dim3(NT / 128, DM / 128), 256, GSMEM>>>(
            o, bt, bo + l * DM, x, res, DM, DM, DM, DM, 1,
            0, 0, 0, 0, 0, 0, 1 | 2);
        ln_kernel<<<NT, 256>>>(res, ln1g + l * DM, ln1b + l * DM, x, xr);

        // FFN
        tr32v<<<dim3(DM / 32, DFF / 32, 1), 256>>>(W1 + (long)l * DM * DFF, bt, DM, DFF, DFF, 1, 0, 0);
        gemm_tc<<<dim3(NT / 128, DFF / 128), 256, GSMEM>>>(
            xr, bt, b1 + l * DFF, nullptr, ffn, DM, DM, DM, DFF, 1,
            0, 0, 0, 0, 0, 0, 1 | 4 | 16);
        tr32v<<<dim3(DFF / 32, DM / 32, 1), 256>>>(W2 + (long)l * DFF * DM, bt, DFF, DM, DM, 1, 0, 0);
        gemm_tc<<<dim3(NT / 128, DM / 128), 256, GSMEM>>>(
            ffn, bt, b2 + l * DM, x, res, DFF, DFF, DFF, DM, 1,
            0, 0, 0, 0, 0, 0, 1 | 2);
        ln_kernel<<<NT, 256>>>(res, ln2g + l * DM, ln2b + l * DM, x, xr);
    }

    // final vocab projection
    tr32v<<<dim3(DM / 32, NV / 32, 1), 256>>>(Wout, bt, DM, NV, NV, 1, 0, 0);
    gemm_tc<<<dim3(NT / 128, NV / 128), 256, GSMEM>>>(
        xr, bt, bout, nullptr, out, DM, DM, DM, NV, 1,
        0, 0, 0, 0, 0, 0, 1);
}